// round 8
// baseline (speedup 1.0000x reference)
#include <cuda_runtime.h>

// ---------------------------------------------------------------------------
// Problem: B=64, S=1024, H=256, NF=C=256, K=7, POOL=3, layer==1 (no pad).
// Inputs (metadata order):
//  0 x[64,1024,256] f32   1 layer(int)      2 gru_kernel_f[256,768]
//  3 gru_rec_f[256,768]   4 gru_bias_f[2,768]
//  5 gru_kernel_b[256,768] 6 gru_rec_b[256,768] 7 gru_bias_b[2,768]
//  8 Wa[512,65536]        9 Wb[256,1792]    10 conv_bias[256]
// Output: [64, 341, 256] f32
// ---------------------------------------------------------------------------

static constexpr int Bn = 64, Sn = 1024, Hn = 256, NFn = 256, Kn = 7;

// -------------------- static device scratch (no allocation) ----------------
__device__ float    g_xT[Sn * Bn * 256];          //  67 MB  [s][b][c]
__device__ float    g_xp[2][Sn * Bn * 768];       // 403 MB  [dir][s*64+b][768]
__device__ float    g_h[2][2][Bn * Hn];           // tiny    [dir][pingpong][b][h]
__device__ float    g_a[Bn * NFn * Hn];           //  17 MB  [b][n*256+e]
__device__ float    g_F[Bn * Kn * 256 * 256];     // 117 MB  [b][k][m][n]
__device__ float    g_y[Bn * Sn * NFn];           //  67 MB  [b][s][n]
__device__ unsigned g_arrive;

// ---------------------------------------------------------------------------
// K1: transpose x[b][s][c] -> xT[s][b][c]
// ---------------------------------------------------------------------------
__global__ void transpose_kernel(const float* __restrict__ x)
{
    int s = blockIdx.x, b = blockIdx.y;
    int c4 = threadIdx.x;                  // 64 threads, one float4 each
    float4 v = ((const float4*)(x + (b * Sn + s) * 256))[c4];
    ((float4*)(g_xT + (s * Bn + b) * 256))[c4] = v;
}

// ---------------------------------------------------------------------------
// K2: reset barrier counter + zero h state (runs every launch -> replay-safe)
// ---------------------------------------------------------------------------
__global__ void reset_kernel()
{
    int i = blockIdx.x * blockDim.x + threadIdx.x;  // 65536 threads
    if (i == 0) g_arrive = 0u;
    ((float*)g_h)[i] = 0.f;                          // 2*2*64*256 = 65536
}

// ---------------------------------------------------------------------------
// Generic 128x64-tile SGEMM, 256 threads, 8x4 per thread, BK=16.
// MODE 0: xp projection.  A=g_xT [65536,256], B=Wk [256,768],
//         C=g_xp[dir] (+bias row0).           grid (512,12,1)
// MODE 1: hyper_b.        A=g_a+b*65536 [256,256], B=Wb [256,1792],
//         C scattered -> g_F[b][k][m][n].     grid (2,28,64)
// MODE 2: dynamic conv.   A virtual (im2col of xT, SAME pad), K=1792,
//         B=g_F[b], C=g_y[b].                 grid (8,4,64)
// ---------------------------------------------------------------------------
template <int MODE>
__global__ __launch_bounds__(256) void gemm128x64(const float* __restrict__ Wmat,
                                                  const float* __restrict__ bias,
                                                  int dir)
{
    constexpr int KDIM = (MODE == 2) ? 1792 : 256;
    constexpr int LDB  = (MODE == 0) ? 768 : (MODE == 1) ? 1792 : 256;

    __shared__ float As[16][132];   // [k][row], padded
    __shared__ float Bs[16][64];    // [k][col]

    const int tid     = threadIdx.x;
    const int rowBase = blockIdx.x * 128;
    const int colBase = blockIdx.y * 64;
    const int bz      = blockIdx.z;

    const int r    = tid >> 1;            // 0..127 : A row within tile
    const int hf8  = (tid & 1) * 8;       // 0 or 8 : A k-subgroup
    const int brow = tid >> 4;            // 0..15  : B k row
    const int bc   = (tid & 15) * 4;      // B col group
    const int tx   = tid & 15;            // compute col group (4 cols)
    const int ty   = tid >> 4;            // compute row group (8 rows)

    float acc[8][4];
#pragma unroll
    for (int i = 0; i < 8; i++)
#pragma unroll
        for (int j = 0; j < 4; j++) acc[i][j] = 0.f;

    const float* Bbase;
    if constexpr (MODE == 2) Bbase = g_F + bz * (Kn * 256 * 256);
    else                     Bbase = Wmat;

    for (int k0 = 0; k0 < KDIM; k0 += 16) {
        // ---- fetch A fragment into registers -------------------------------
        float4 v0, v1;
        if constexpr (MODE == 0) {
            const float* p = g_xT + (rowBase + r) * 256 + k0 + hf8;
            v0 = *(const float4*)p;  v1 = *(const float4*)(p + 4);
        } else if constexpr (MODE == 1) {
            const float* p = g_a + bz * 65536 + (rowBase + r) * 256 + k0 + hf8;
            v0 = *(const float4*)p;  v1 = *(const float4*)(p + 4);
        } else {
            int kp = k0 >> 8;                      // conv tap 0..6 (tile stays in one tap)
            int s2 = rowBase + r + kp - 3;         // SAME pad
            if (s2 >= 0 && s2 < Sn) {
                const float* p = g_xT + (s2 * Bn + bz) * 256 + (k0 & 255) + hf8;
                v0 = *(const float4*)p;  v1 = *(const float4*)(p + 4);
            } else {
                v0 = make_float4(0.f, 0.f, 0.f, 0.f);  v1 = v0;
            }
        }
        // ---- fetch B fragment ---------------------------------------------
        float4 bv = *(const float4*)(Bbase + (k0 + brow) * LDB + colBase + bc);

        __syncthreads();   // previous tile's compute done before overwrite
        As[hf8 + 0][r] = v0.x;  As[hf8 + 1][r] = v0.y;
        As[hf8 + 2][r] = v0.z;  As[hf8 + 3][r] = v0.w;
        As[hf8 + 4][r] = v1.x;  As[hf8 + 5][r] = v1.y;
        As[hf8 + 6][r] = v1.z;  As[hf8 + 7][r] = v1.w;
        *(float4*)&Bs[brow][bc] = bv;
        __syncthreads();

#pragma unroll
        for (int kk = 0; kk < 16; kk++) {
            float4 a0 = *(const float4*)&As[kk][ty * 8];
            float4 a1 = *(const float4*)&As[kk][ty * 8 + 4];
            float4 b4 = *(const float4*)&Bs[kk][tx * 4];
            float av[8] = {a0.x, a0.y, a0.z, a0.w, a1.x, a1.y, a1.z, a1.w};
            float bw[4] = {b4.x, b4.y, b4.z, b4.w};
#pragma unroll
            for (int i = 0; i < 8; i++)
#pragma unroll
                for (int j = 0; j < 4; j++) acc[i][j] += av[i] * bw[j];
        }
    }

    // ---- epilogue ----------------------------------------------------------
    if constexpr (MODE == 0) {
        float*  outp = g_xp[dir];
        float4  bb   = *(const float4*)(bias + colBase + tx * 4);
#pragma unroll
        for (int i = 0; i < 8; i++) {
            float4 o = make_float4(acc[i][0] + bb.x, acc[i][1] + bb.y,
                                   acc[i][2] + bb.z, acc[i][3] + bb.w);
            *(float4*)(outp + (rowBase + ty * 8 + i) * 768 + colBase + tx * 4) = o;
        }
    } else if constexpr (MODE == 1) {
        // out(n=row, f=col); f = m*7+k ; store F[b][k][m][n]
#pragma unroll
        for (int j = 0; j < 4; j++) {
            int col = colBase + tx * 4 + j;
            int k = col % 7, m = col / 7;
            float* dst = g_F + ((bz * 7 + k) * 256 + m) * 256 + rowBase + ty * 8;
#pragma unroll
            for (int i = 0; i < 8; i++) dst[i] = acc[i][j];
        }
    } else {
        float* outp = g_y + bz * (Sn * 256);
#pragma unroll
        for (int i = 0; i < 8; i++) {
            float4 o = make_float4(acc[i][0], acc[i][1], acc[i][2], acc[i][3]);
            *(float4*)(outp + (rowBase + ty * 8 + i) * 256 + colBase + tx * 4) = o;
        }
    }
}

// ---------------------------------------------------------------------------
// K4: persistent GRU, both directions. 128 blocks x 128 threads (all resident).
// Block = (dir, 4 hidden units). Per step: [64,256]@[256,12] GEMM from smem,
// gates, h ping-pong through L2 (__ldcg), grid barrier.
// ---------------------------------------------------------------------------
static constexpr int GRU_SMEM = (64 * 264 + 12 * 260) * 4;   // 80064 B

__global__ __launch_bounds__(128, 1) void gru_kernel(const float* __restrict__ rec_f,
                                                     const float* __restrict__ rec_b,
                                                     const float* __restrict__ bias_f,
                                                     const float* __restrict__ bias_b)
{
    extern __shared__ float sm[];
    float* hs = sm;                 // [64][264] padded h copy
    float* Wc = sm + 64 * 264;      // [12][260] weight columns (g*4+u)

    const int bid = blockIdx.x;
    const int dir = bid >> 6;
    const int cb  = bid & 63;
    const int u0  = cb * 4;
    const int tid = threadIdx.x;

    const float* rec  = dir ? rec_b  : rec_f;
    const float* bias = dir ? bias_b : bias_f;
    const float* xp   = g_xp[dir];

    // cache the 12 recurrent-weight columns this block owns
    for (int i = tid; i < 12 * 256; i += 128) {
        int c = i & 255, j = i >> 8;          // j = g*4+u
        int g = j >> 2,  u = j & 3;
        Wc[j * 260 + c] = rec[c * 768 + g * 256 + u0 + u];
    }

    const int u  = tid & 3;
    const int rg = tid >> 2;
    const int b0 = rg * 2, b1 = b0 + 1;
    const int hu = u0 + u;
    const float bz_ = bias[768 + hu];
    const float br_ = bias[768 + 256 + hu];
    const float bn_ = bias[768 + 512 + hu];

    const float4* wz = (const float4*)&Wc[(0 * 4 + u) * 260];
    const float4* wr = (const float4*)&Wc[(1 * 4 + u) * 260];
    const float4* wn = (const float4*)&Wc[(2 * 4 + u) * 260];

    for (int t = 0; t < 1024; t++) {
        int s = dir ? (1023 - t) : t;
        const float* hrd = g_h[dir][t & 1];
        float*       hwr = g_h[dir][(t & 1) ^ 1];

        // stage h[64][256] into smem (L2 reads; L1 would be stale)
#pragma unroll 8
        for (int i = 0; i < 32; i++) {
            int lin = tid + i * 128;          // float4 index 0..4095
            int b = lin >> 6, c4 = lin & 63;
            float4 v = __ldcg((const float4*)hrd + lin);
            *(float4*)&hs[b * 264 + c4 * 4] = v;
        }
        __syncthreads();   // also covers Wc init on t==0

        int xb0 = (s * 64 + b0) * 768;
        int xb1 = xb0 + 768;
        float xz0 = xp[xb0 + hu], xr0 = xp[xb0 + 256 + hu], xh0 = xp[xb0 + 512 + hu];
        float xz1 = xp[xb1 + hu], xr1 = xp[xb1 + 256 + hu], xh1 = xp[xb1 + 512 + hu];

        float az0 = 0, ar0 = 0, an0 = 0, az1 = 0, ar1 = 0, an1 = 0;
        const float4* h0p = (const float4*)&hs[b0 * 264];
        const float4* h1p = (const float4*)&hs[b1 * 264];
#pragma unroll 4
        for (int c4 = 0; c4 < 64; c4++) {
            float4 hA = h0p[c4], hB = h1p[c4];
            float4 z4 = wz[c4],  r4 = wr[c4], n4 = wn[c4];
            az0 += hA.x * z4.x + hA.y * z4.y + hA.z * z4.z + hA.w * z4.w;
            ar0 += hA.x * r4.x + hA.y * r4.y + hA.z * r4.z + hA.w * r4.w;
            an0 += hA.x * n4.x + hA.y * n4.y + hA.z * n4.z + hA.w * n4.w;
            az1 += hB.x * z4.x + hB.y * z4.y + hB.z * z4.z + hB.w * z4.w;
            ar1 += hB.x * r4.x + hB.y * r4.y + hB.z * r4.z + hB.w * r4.w;
            an1 += hB.x * n4.x + hB.y * n4.y + hB.z * n4.z + hB.w * n4.w;
        }

        float z0 = 1.f / (1.f + __expf(-(xz0 + az0 + bz_)));
        float r0 = 1.f / (1.f + __expf(-(xr0 + ar0 + br_)));
        float hh0 = tanhf(xh0 + r0 * (an0 + bn_));
        float hp0 = hs[b0 * 264 + hu];
        float z1 = 1.f / (1.f + __expf(-(xz1 + az1 + bz_)));
        float r1 = 1.f / (1.f + __expf(-(xr1 + ar1 + br_)));
        float hh1 = tanhf(xh1 + r1 * (an1 + bn_));
        float hp1 = hs[b1 * 264 + hu];

        hwr[b0 * 256 + hu] = z0 * hp0 + (1.f - z0) * hh0;
        hwr[b1 * 256 + hu] = z1 * hp1 + (1.f - z1) * hh1;

        __threadfence();
        __syncthreads();
        if (tid == 0) {
            atomicAdd(&g_arrive, 1u);
            unsigned target = (unsigned)(t + 1) * 128u;
            while (*((volatile unsigned*)&g_arrive) < target) {}
        }
        __syncthreads();
    }
    // final states live in g_h[dir][0]
}

// ---------------------------------------------------------------------------
// K5: a = c @ Wa ; c = [hf | hb] [64,512], Wa [512,65536] -> g_a[64][65536]
// 64x64 tile, 256 threads, 4x4 per thread.  grid (1024)
// ---------------------------------------------------------------------------
__global__ __launch_bounds__(256) void hyperA_kernel(const float* __restrict__ Wa)
{
    __shared__ float As[16][68];
    __shared__ float Bs[16][64];
    const int tid = threadIdx.x;
    const int colBase = blockIdx.x * 64;
    const int bb = tid & 63, cg = tid >> 6;       // A loader
    const int brow = tid >> 4, bc = (tid & 15) * 4;
    const int tx = tid & 15, ty = tid >> 4;

    float acc[4][4];
#pragma unroll
    for (int i = 0; i < 4; i++)
#pragma unroll
        for (int j = 0; j < 4; j++) acc[i][j] = 0.f;

    for (int k0 = 0; k0 < 512; k0 += 16) {
        int j0 = k0 + cg * 4;
        const float* src = (j0 < 256) ? (g_h[0][0] + bb * 256 + j0)
                                      : (g_h[1][0] + bb * 256 + (j0 - 256));
        float4 v  = *(const float4*)src;
        float4 bv = *(const float4*)(Wa + (k0 + brow) * 65536 + colBase + bc);

        __syncthreads();
        As[cg * 4 + 0][bb] = v.x;  As[cg * 4 + 1][bb] = v.y;
        As[cg * 4 + 2][bb] = v.z;  As[cg * 4 + 3][bb] = v.w;
        *(float4*)&Bs[brow][bc] = bv;
        __syncthreads();

#pragma unroll
        for (int kk = 0; kk < 16; kk++) {
            float4 a4 = *(const float4*)&As[kk][ty * 4];
            float4 b4 = *(const float4*)&Bs[kk][tx * 4];
            float av[4] = {a4.x, a4.y, a4.z, a4.w};
            float bw[4] = {b4.x, b4.y, b4.z, b4.w};
#pragma unroll
            for (int i = 0; i < 4; i++)
#pragma unroll
                for (int j = 0; j < 4; j++) acc[i][j] += av[i] * bw[j];
        }
    }
#pragma unroll
    for (int i = 0; i < 4; i++) {
        float4 o = make_float4(acc[i][0], acc[i][1], acc[i][2], acc[i][3]);
        *(float4*)(g_a + (ty * 4 + i) * 65536 + colBase + tx * 4) = o;
    }
}

// ---------------------------------------------------------------------------
// K8: bias + relu + maxpool(3).  out[b][p][n] = relu(max_q y[b][3p+q][n] + bias[n])
// ---------------------------------------------------------------------------
__global__ void pool_kernel(float* __restrict__ out, const float* __restrict__ bias)
{
    int n = threadIdx.x;            // 256
    int p = blockIdx.x;             // 341
    int b = blockIdx.y;             // 64
    const float* y = g_y + ((b * Sn) + p * 3) * 256 + n;
    float v = fmaxf(fmaxf(y[0], y[256]), y[512]) + bias[n];
    out[(b * 341 + p) * 256 + n] = fmaxf(v, 0.f);
}

// ---------------------------------------------------------------------------
extern "C" void kernel_launch(void* const* d_in, const int* in_sizes, int n_in,
                              void* d_out, int out_size)
{
    (void)in_sizes; (void)n_in; (void)out_size;
    const float* x     = (const float*)d_in[0];
    const float* gk_f  = (const float*)d_in[2];
    const float* gr_f  = (const float*)d_in[3];
    const float* gb_f  = (const float*)d_in[4];
    const float* gk_b  = (const float*)d_in[5];
    const float* gr_b  = (const float*)d_in[6];
    const float* gb_b  = (const float*)d_in[7];
    const float* Wa    = (const float*)d_in[8];
    const float* Wb    = (const float*)d_in[9];
    const float* cbias = (const float*)d_in[10];
    float* out = (float*)d_out;

    cudaFuncSetAttribute(gru_kernel, cudaFuncAttributeMaxDynamicSharedMemorySize,
                         GRU_SMEM);

    transpose_kernel<<<dim3(1024, 64), 64>>>(x);
    gemm128x64<0><<<dim3(512, 12, 1), 256>>>(gk_f, gb_f, 0);
    gemm128x64<0><<<dim3(512, 12, 1), 256>>>(gk_b, gb_b, 1);
    reset_kernel<<<256, 256>>>();
    gru_kernel<<<128, 128, GRU_SMEM>>>(gr_f, gr_b, gb_f, gb_b);
    hyperA_kernel<<<1024, 256>>>(Wa);
    gemm128x64<1><<<dim3(2, 28, 64), 256>>>(Wb, nullptr, 0);
    gemm128x64<2><<<dim3(8, 4, 64), 256>>>(nullptr, nullptr, 0);
    pool_kernel<<<dim3(341, 64), 256>>>(out, cbias);
}

// round 9
// speedup vs baseline: 1.0133x; 1.0133x over previous
#include <cuda_runtime.h>

// ---------------------------------------------------------------------------
// B=64, S=1024, H=256, NF=C=256, K=7, POOL=3, layer==1 (no pad).
// Inputs: 0 x[64,1024,256] 1 layer 2 gk_f[256,768] 3 gr_f[256,768] 4 gb_f[2,768]
//         5 gk_b 6 gr_b 7 gb_b 8 Wa[512,65536] 9 Wb[256,1792] 10 conv_bias[256]
// Output: [64, 341, 256] f32
//
// Restructured conv:  y[b][s][n] = sum_e a[b][n][e] * Z[b][s][e],
//   Z[b][s][e] = sum_{k,m} x[b][s+k-3][m] * Wb[e][m*7+k]   (static conv)
// ---------------------------------------------------------------------------

static constexpr int Bn = 64, Sn = 1024, Hn = 256, NFn = 256, Kn = 7;

// -------------------- static device scratch --------------------------------
__device__ float    g_xT[Sn * Bn * 256];          //  67 MB  [s][b][c]
__device__ float    g_xp[2][Sn * Bn * 768];       // 403 MB  [dir][s*64+b][768]
__device__ float    g_h[2][2][Bn * Hn];           //         [dir][pp][b][h]
__device__ float    g_Bz[Kn * 256 * 256];         // 1.8 MB  [k*256+m][e]
__device__ float    g_Z[Sn * Bn * 256];           //  67 MB  [s*64+b][e]
__device__ float    g_aT[Bn * 256 * 256];         //  17 MB  [b][e][n]
__device__ float    g_y[Bn * Sn * NFn];           //  67 MB  [b][s][n]
__device__ unsigned g_arrive;

// ---------------------------------------------------------------------------
// transpose x[b][s][c] -> xT[s][b][c]
// ---------------------------------------------------------------------------
__global__ void transpose_kernel(const float* __restrict__ x)
{
    int s = blockIdx.x, b = blockIdx.y;
    int c4 = threadIdx.x;
    float4 v = ((const float4*)(x + (b * Sn + s) * 256))[c4];
    ((float4*)(g_xT + (s * Bn + b) * 256))[c4] = v;
}

// ---------------------------------------------------------------------------
// reset barrier counter + zero h state (every launch -> graph-replay safe)
// ---------------------------------------------------------------------------
__global__ void reset_kernel()
{
    int i = blockIdx.x * blockDim.x + threadIdx.x;
    if (i == 0) g_arrive = 0u;
    ((float*)g_h)[i] = 0.f;                       // 2*2*64*256 = 65536
}

// ---------------------------------------------------------------------------
// Bz[(k*256+m)][e] = Wb[e][m*7+k]
// ---------------------------------------------------------------------------
__global__ void prep_bz_kernel(const float* __restrict__ Wb)
{
    int j = blockIdx.x;                 // 0..1791
    int e = threadIdx.x;                // 0..255
    int k = j >> 8, m = j & 255;
    g_Bz[j * 256 + e] = Wb[e * 1792 + m * 7 + k];
}

// ---------------------------------------------------------------------------
// 128x128-tile SGEMM, 256 threads, 8x8/thread, BK=16, double-buffered smem.
// MODE 0: xp = xT @ Wk + bias.   A rows n=s*64+b, K=256, LDB=768. grid(512,6)
// MODE 1: Z = im2col(xT) @ Bz.   K=1792, LDB=256.                 grid(512,2)
// MODE 2: y[b] = Z[:,b,:] @ aT[b]. K=256, LDB=256.                grid(8,2,64)
// ---------------------------------------------------------------------------
template <int MODE>
__global__ __launch_bounds__(256, 2) void gemm128(const float* __restrict__ Bmat,
                                                  const float* __restrict__ bias,
                                                  int dir)
{
    constexpr int KDIM = (MODE == 1) ? 1792 : 256;
    constexpr int LDB  = (MODE == 0) ? 768 : 256;
    constexpr int NT   = KDIM / 16;

    __shared__ float As[2][16][132];
    __shared__ float Bs[2][16][128];

    const int tid     = threadIdx.x;
    const int rowBase = blockIdx.x * 128;
    const int colBase = blockIdx.y * 128;
    const int bz      = blockIdx.z;

    const int r    = tid >> 1;            // A row 0..127
    const int hf8  = (tid & 1) * 8;       // A k subgroup
    const int brow = tid >> 4;            // B k row 0..15
    const int bc   = (tid & 15) * 8;      // B col group
    const int tx   = tid & 15;            // compute col group (8 cols)
    const int ty   = tid >> 4;            // compute row group (8 rows)

    const float* Bp;
    if constexpr (MODE == 0)      Bp = Bmat;
    else if constexpr (MODE == 1) Bp = g_Bz;
    else                          Bp = g_aT + bz * 65536;

    float acc[8][8];
#pragma unroll
    for (int i = 0; i < 8; i++)
#pragma unroll
        for (int j = 0; j < 8; j++) acc[i][j] = 0.f;

    float4 a0, a1, b0, b1;

    auto loadFrag = [&](int k0) {
        if constexpr (MODE == 0) {
            const float* p = g_xT + (rowBase + r) * 256 + k0 + hf8;
            a0 = *(const float4*)p;  a1 = *(const float4*)(p + 4);
        } else if constexpr (MODE == 1) {
            int j  = k0 + hf8;                 // col in [0,1792), tap-safe (j%16∈{0,8})
            int kp = j >> 8;                   // conv tap 0..6
            int srcrow = rowBase + r + (kp - 3) * 64;   // n + (k-3)*64
            if (srcrow >= 0 && srcrow < 65536) {
                const float* p = g_xT + srcrow * 256 + (j & 255);
                a0 = *(const float4*)p;  a1 = *(const float4*)(p + 4);
            } else {
                a0 = make_float4(0.f, 0.f, 0.f, 0.f);  a1 = a0;
            }
        } else {
            const float* p = g_Z + ((rowBase + r) * 64 + bz) * 256 + k0 + hf8;
            a0 = *(const float4*)p;  a1 = *(const float4*)(p + 4);
        }
        const float* q = Bp + (k0 + brow) * LDB + colBase + bc;
        b0 = *(const float4*)q;  b1 = *(const float4*)(q + 4);
    };

    auto storeFrag = [&](int buf) {
        As[buf][hf8 + 0][r] = a0.x;  As[buf][hf8 + 1][r] = a0.y;
        As[buf][hf8 + 2][r] = a0.z;  As[buf][hf8 + 3][r] = a0.w;
        As[buf][hf8 + 4][r] = a1.x;  As[buf][hf8 + 5][r] = a1.y;
        As[buf][hf8 + 6][r] = a1.z;  As[buf][hf8 + 7][r] = a1.w;
        *(float4*)&Bs[buf][brow][bc]     = b0;
        *(float4*)&Bs[buf][brow][bc + 4] = b1;
    };

    loadFrag(0);
    storeFrag(0);
    __syncthreads();

    for (int t = 0; t < NT; t++) {
        int cur = t & 1;
        if (t + 1 < NT) loadFrag((t + 1) * 16);

#pragma unroll
        for (int kk = 0; kk < 16; kk++) {
            float4 x0 = *(const float4*)&As[cur][kk][ty * 8];
            float4 x1 = *(const float4*)&As[cur][kk][ty * 8 + 4];
            float4 y0 = *(const float4*)&Bs[cur][kk][tx * 8];
            float4 y1 = *(const float4*)&Bs[cur][kk][tx * 8 + 4];
            float av[8] = {x0.x, x0.y, x0.z, x0.w, x1.x, x1.y, x1.z, x1.w};
            float bw[8] = {y0.x, y0.y, y0.z, y0.w, y1.x, y1.y, y1.z, y1.w};
#pragma unroll
            for (int i = 0; i < 8; i++)
#pragma unroll
                for (int j = 0; j < 8; j++) acc[i][j] += av[i] * bw[j];
        }

        if (t + 1 < NT) storeFrag(cur ^ 1);
        __syncthreads();
    }

    // ---- epilogue ----------------------------------------------------------
    if constexpr (MODE == 0) {
        float* outp = g_xp[dir];
        float4 bb0 = *(const float4*)(bias + colBase + tx * 8);
        float4 bb1 = *(const float4*)(bias + colBase + tx * 8 + 4);
#pragma unroll
        for (int i = 0; i < 8; i++) {
            float* d = outp + (rowBase + ty * 8 + i) * 768 + colBase + tx * 8;
            *(float4*)d       = make_float4(acc[i][0] + bb0.x, acc[i][1] + bb0.y,
                                            acc[i][2] + bb0.z, acc[i][3] + bb0.w);
            *(float4*)(d + 4) = make_float4(acc[i][4] + bb1.x, acc[i][5] + bb1.y,
                                            acc[i][6] + bb1.z, acc[i][7] + bb1.w);
        }
    } else if constexpr (MODE == 1) {
#pragma unroll
        for (int i = 0; i < 8; i++) {
            float* d = g_Z + (rowBase + ty * 8 + i) * 256 + colBase + tx * 8;
            *(float4*)d       = make_float4(acc[i][0], acc[i][1], acc[i][2], acc[i][3]);
            *(float4*)(d + 4) = make_float4(acc[i][4], acc[i][5], acc[i][6], acc[i][7]);
        }
    } else {
        float* outp = g_y + bz * (Sn * 256);
#pragma unroll
        for (int i = 0; i < 8; i++) {
            float* d = outp + (rowBase + ty * 8 + i) * 256 + colBase + tx * 8;
            *(float4*)d       = make_float4(acc[i][0], acc[i][1], acc[i][2], acc[i][3]);
            *(float4*)(d + 4) = make_float4(acc[i][4], acc[i][5], acc[i][6], acc[i][7]);
        }
    }
}

// ---------------------------------------------------------------------------
// persistent GRU, both directions (unchanged from R7 — known correct).
// ---------------------------------------------------------------------------
static constexpr int GRU_SMEM = (64 * 264 + 12 * 260) * 4;   // 80064 B

__global__ __launch_bounds__(128, 1) void gru_kernel(const float* __restrict__ rec_f,
                                                     const float* __restrict__ rec_b,
                                                     const float* __restrict__ bias_f,
                                                     const float* __restrict__ bias_b)
{
    extern __shared__ float sm[];
    float* hs = sm;                 // [64][264]
    float* Wc = sm + 64 * 264;      // [12][260]

    const int bid = blockIdx.x;
    const int dir = bid >> 6;
    const int cb  = bid & 63;
    const int u0  = cb * 4;
    const int tid = threadIdx.x;

    const float* rec  = dir ? rec_b  : rec_f;
    const float* bias = dir ? bias_b : bias_f;
    const float* xp   = g_xp[dir];

    for (int i = tid; i < 12 * 256; i += 128) {
        int c = i & 255, j = i >> 8;
        int g = j >> 2,  u = j & 3;
        Wc[j * 260 + c] = rec[c * 768 + g * 256 + u0 + u];
    }

    const int u  = tid & 3;
    const int rg = tid >> 2;
    const int b0 = rg * 2, b1 = b0 + 1;
    const int hu = u0 + u;
    const float bz_ = bias[768 + hu];
    const float br_ = bias[768 + 256 + hu];
    const float bn_ = bias[768 + 512 + hu];

    const float4* wz = (const float4*)&Wc[(0 * 4 + u) * 260];
    const float4* wr = (const float4*)&Wc[(1 * 4 + u) * 260];
    const float4* wn = (const float4*)&Wc[(2 * 4 + u) * 260];

    for (int t = 0; t < 1024; t++) {
        int s = dir ? (1023 - t) : t;
        const float* hrd = g_h[dir][t & 1];
        float*       hwr = g_h[dir][(t & 1) ^ 1];

#pragma unroll 8
        for (int i = 0; i < 32; i++) {
            int lin = tid + i * 128;
            int b = lin >> 6, c4 = lin & 63;
            float4 v = __ldcg((const float4*)hrd + lin);
            *(float4*)&hs[b * 264 + c4 * 4] = v;
        }
        __syncthreads();

        int xb0 = (s * 64 + b0) * 768;
        int xb1 = xb0 + 768;
        float xz0 = xp[xb0 + hu], xr0 = xp[xb0 + 256 + hu], xh0 = xp[xb0 + 512 + hu];
        float xz1 = xp[xb1 + hu], xr1 = xp[xb1 + 256 + hu], xh1 = xp[xb1 + 512 + hu];

        float az0 = 0, ar0 = 0, an0 = 0, az1 = 0, ar1 = 0, an1 = 0;
        const float4* h0p = (const float4*)&hs[b0 * 264];
        const float4* h1p = (const float4*)&hs[b1 * 264];
#pragma unroll 4
        for (int c4 = 0; c4 < 64; c4++) {
            float4 hA = h0p[c4], hB = h1p[c4];
            float4 z4 = wz[c4],  r4 = wr[c4], n4 = wn[c4];
            az0 += hA.x * z4.x + hA.y * z4.y + hA.z * z4.z + hA.w * z4.w;
            ar0 += hA.x * r4.x + hA.y * r4.y + hA.z * r4.z + hA.w * r4.w;
            an0 += hA.x * n4.x + hA.y * n4.y + hA.z * n4.z + hA.w * n4.w;
            az1 += hB.x * z4.x + hB.y * z4.y + hB.z * z4.z + hB.w * z4.w;
            ar1 += hB.x * r4.x + hB.y * r4.y + hB.z * r4.z + hB.w * r4.w;
            an1 += hB.x * n4.x + hB.y * n4.y + hB.z * n4.z + hB.w * n4.w;
        }

        float z0 = 1.f / (1.f + __expf(-(xz0 + az0 + bz_)));
        float r0 = 1.f / (1.f + __expf(-(xr0 + ar0 + br_)));
        float hh0 = tanhf(xh0 + r0 * (an0 + bn_));
        float hp0 = hs[b0 * 264 + hu];
        float z1 = 1.f / (1.f + __expf(-(xz1 + az1 + bz_)));
        float r1 = 1.f / (1.f + __expf(-(xr1 + ar1 + br_)));
        float hh1 = tanhf(xh1 + r1 * (an1 + bn_));
        float hp1 = hs[b1 * 264 + hu];

        hwr[b0 * 256 + hu] = z0 * hp0 + (1.f - z0) * hh0;
        hwr[b1 * 256 + hu] = z1 * hp1 + (1.f - z1) * hh1;

        __threadfence();
        __syncthreads();
        if (tid == 0) {
            atomicAdd(&g_arrive, 1u);
            unsigned target = (unsigned)(t + 1) * 128u;
            while (*((volatile unsigned*)&g_arrive) < target) {}
        }
        __syncthreads();
    }
}

// ---------------------------------------------------------------------------
// aT[b][e][n] = sum_c c[b][c] * Wa[c][n*256+e].  64x64 tiles, grid(1024).
// ---------------------------------------------------------------------------
__global__ __launch_bounds__(256) void hyperAT_kernel(const float* __restrict__ Wa)
{
    __shared__ float As[16][68];
    __shared__ float Bs[16][64];
    const int tid = threadIdx.x;
    const int colBase = blockIdx.x * 64;
    const int bb = tid & 63, cg = tid >> 6;
    const int brow = tid >> 4, bc = (tid & 15) * 4;
    const int tx = tid & 15, ty = tid >> 4;

    float acc[4][4];
#pragma unroll
    for (int i = 0; i < 4; i++)
#pragma unroll
        for (int j = 0; j < 4; j++) acc[i][j] = 0.f;

    for (int k0 = 0; k0 < 512; k0 += 16) {
        int j0 = k0 + cg * 4;
        const float* src = (j0 < 256) ? (g_h[0][0] + bb * 256 + j0)
                                      : (g_h[1][0] + bb * 256 + (j0 - 256));
        float4 v  = *(const float4*)src;
        float4 bv = *(const float4*)(Wa + (k0 + brow) * 65536 + colBase + bc);

        __syncthreads();
        As[cg * 4 + 0][bb] = v.x;  As[cg * 4 + 1][bb] = v.y;
        As[cg * 4 + 2][bb] = v.z;  As[cg * 4 + 3][bb] = v.w;
        *(float4*)&Bs[brow][bc] = bv;
        __syncthreads();

#pragma unroll
        for (int kk = 0; kk < 16; kk++) {
            float4 a4 = *(const float4*)&As[kk][ty * 4];
            float4 b4 = *(const float4*)&Bs[kk][tx * 4];
            float av[4] = {a4.x, a4.y, a4.z, a4.w};
            float bw[4] = {b4.x, b4.y, b4.z, b4.w};
#pragma unroll
            for (int i = 0; i < 4; i++)
#pragma unroll
                for (int j = 0; j < 4; j++) acc[i][j] += av[i] * bw[j];
        }
    }
    // transposed store: col j -> (n = j/256, e = j%256); aT[b][e][n]
#pragma unroll
    for (int j = 0; j < 4; j++) {
        int jc = colBase + tx * 4 + j;
        int n = jc >> 8, e = jc & 255;
#pragma unroll
        for (int i = 0; i < 4; i++)
            g_aT[(ty * 4 + i) * 65536 + e * 256 + n] = acc[i][j];
    }
}

// ---------------------------------------------------------------------------
// bias + relu + maxpool(3)
// ---------------------------------------------------------------------------
__global__ void pool_kernel(float* __restrict__ out, const float* __restrict__ bias)
{
    int n = threadIdx.x;            // 256
    int p = blockIdx.x;             // 341
    int b = blockIdx.y;             // 64
    const float* y = g_y + ((b * Sn) + p * 3) * 256 + n;
    float v = fmaxf(fmaxf(y[0], y[256]), y[512]) + bias[n];
    out[(b * 341 + p) * 256 + n] = fmaxf(v, 0.f);
}

// ---------------------------------------------------------------------------
extern "C" void kernel_launch(void* const* d_in, const int* in_sizes, int n_in,
                              void* d_out, int out_size)
{
    (void)in_sizes; (void)n_in; (void)out_size;
    const float* x     = (const float*)d_in[0];
    const float* gk_f  = (const float*)d_in[2];
    const float* gr_f  = (const float*)d_in[3];
    const float* gb_f  = (const float*)d_in[4];
    const float* gk_b  = (const float*)d_in[5];
    const float* gr_b  = (const float*)d_in[6];
    const float* gb_b  = (const float*)d_in[7];
    const float* Wa    = (const float*)d_in[8];
    const float* Wb    = (const float*)d_in[9];
    const float* cbias = (const float*)d_in[10];
    float* out = (float*)d_out;

    cudaFuncSetAttribute(gru_kernel, cudaFuncAttributeMaxDynamicSharedMemorySize,
                         GRU_SMEM);

    transpose_kernel<<<dim3(1024, 64), 64>>>(x);
    reset_kernel<<<256, 256>>>();
    gemm128<0><<<dim3(512, 6, 1), 256>>>(gk_f, gb_f, 0);
    gemm128<0><<<dim3(512, 6, 1), 256>>>(gk_b, gb_b, 1);
    gru_kernel<<<128, 128, GRU_SMEM>>>(gr_f, gr_b, gb_f, gb_b);
    prep_bz_kernel<<<1792, 256>>>(Wb);
    gemm128<1><<<dim3(512, 2, 1), 256>>>(nullptr, nullptr, 0);
    hyperAT_kernel<<<1024, 256>>>(Wa);
    gemm128<2><<<dim3(8, 2, 64), 256>>>(nullptr, nullptr, 0);
    pool_kernel<<<dim3(341, 64), 256>>>(out, cbias);
}